// round 4
// baseline (speedup 1.0000x reference)
#include <cuda_runtime.h>
#include <cstdint>

// MoEGRU: B=256, L=1800, F=50, E=4, K=2, H=32, D=64, HU=32
#define NB 256
#define NL 1800
#define NF 50
#define NE 4
#define NH 32
#define ND 64
#define NS 512      // routed chains = B*K
#define TT 40       // time-tile for xg0 GEMM
#define NTILE 45    // 1800/40

typedef unsigned long long ull;

// ---- scratch (static device globals; no allocation allowed) ----
__device__ float g_xg0[(size_t)NS * NL * 96];   // 354 MB: precomputed input gates, layer 0
__device__ float g_M[NE * 96 * NF];             // fused W_in -> Wih0 matrix
__device__ float g_c[NS * 96];                  // per-chain constant (emb/bias folded)
__device__ int   g_ce[NS];                      // chain -> expert
__device__ float g_cw[NS];                      // chain -> routing weight
__device__ float g_predw[NS];                   // weighted per-chain prediction

// ---- packed f32x2 helpers (sm_103a dual-fp32 pipe) ----
__device__ __forceinline__ ull pack2(float lo, float hi) {
    ull r;
    asm("mov.b64 %0, {%1, %2};" : "=l"(r) : "f"(lo), "f"(hi));
    return r;
}
__device__ __forceinline__ void fma2(ull &acc, ull a, ull b) {
    asm("fma.rn.f32x2 %0, %1, %2, %0;" : "+l"(acc) : "l"(a), "l"(b));
}
__device__ __forceinline__ float hsum2(ull v) {
    float lo, hi;
    asm("mov.b64 {%0, %1}, %2;" : "=f"(lo), "=f"(hi) : "l"(v));
    return lo + hi;
}

__device__ __forceinline__ float sigm(float x) { return 1.f / (1.f + __expf(-x)); }
__device__ __forceinline__ float tanh_f(float x) {
    float e = __expf(2.f * x);
    return 1.f - 2.f / (e + 1.f);
}

// ---- K1: gating (top-2 softmax) + chain assignment ----
__global__ void k_gate(const int* __restrict__ horizon, const float* __restrict__ emb,
                       const float* __restrict__ W_gate, const float* __restrict__ b_gate) {
    int b = threadIdx.x;
    const float* ev = emb + (size_t)horizon[b] * ND;
    float l[NE];
#pragma unroll
    for (int e = 0; e < NE; e++) {
        float acc = b_gate[e];
        for (int d = 0; d < ND; d++) acc += W_gate[e * ND + d] * ev[d];
        l[e] = acc;
    }
    int i0 = 0;
#pragma unroll
    for (int e = 1; e < NE; e++) if (l[e] > l[i0]) i0 = e;
    int i1 = -1;
#pragma unroll
    for (int e = 0; e < NE; e++) if (e != i0 && (i1 < 0 || l[e] > l[i1])) i1 = e;
    float ex = __expf(l[i1] - l[i0]);   // l[i0] is the max
    float w0 = 1.f / (1.f + ex);
    g_ce[2 * b] = i0;     g_cw[2 * b] = w0;
    g_ce[2 * b + 1] = i1; g_cw[2 * b + 1] = ex * w0;
}

// ---- K2: M[e][g][f] = sum_d Wih0[e][g][d] * W_in[d][f] ----
__global__ void k_M(const float* __restrict__ Wih0, const float* __restrict__ W_in) {
    int e = blockIdx.x, g = blockIdx.y, f = threadIdx.x;
    if (f >= NF) return;
    float acc = 0.f;
    for (int d = 0; d < ND; d++) acc += Wih0[(e * 96 + g) * ND + d] * W_in[d * NF + f];
    g_M[(e * 96 + g) * NF + f] = acc;
}

// ---- K3: chain constants: (b_in + emb[h_b]) . Wih0 + bih0 (+ bhh0 for r,z) ----
__global__ void k_c(const int* __restrict__ horizon, const float* __restrict__ b_in,
                    const float* __restrict__ emb, const float* __restrict__ Wih0,
                    const float* __restrict__ bih0, const float* __restrict__ bhh0) {
    int s = blockIdx.x, g = threadIdx.x;
    int b = s >> 1, e = g_ce[s];
    __shared__ float v[ND];
    if (g < ND) v[g] = b_in[g] + emb[(size_t)horizon[b] * ND + g];
    __syncthreads();
    float acc = bih0[e * 96 + g] + (g < 64 ? bhh0[e * 96 + g] : 0.f);  // bhh0_n stays with r*gh_n
#pragma unroll 8
    for (int d = 0; d < ND; d++) acc += Wih0[(e * 96 + g) * ND + d] * v[d];
    g_c[s * 96 + g] = acc;
}

// ---- K4: xg0[s][t][g] = x[b,t,:] . M[e][g][:] + c[s][g]  (f32x2 packed) ----
__global__ __launch_bounds__(96) void k_xg0(const float* __restrict__ x) {
    int s = blockIdx.x, tile = blockIdx.y;
    int b = s >> 1, e = g_ce[s];
    int t0 = tile * TT;
    __shared__ __align__(16) float xs[TT * 52];   // 52-float row stride (pad, 8B aligned pairs)
    int tid = threadIdx.x;
    const float* xsrc = x + ((size_t)b * NL + t0) * NF;
    for (int idx = tid; idx < TT * NF; idx += 96)
        xs[(idx / NF) * 52 + (idx % NF)] = xsrc[idx];

    ull m2[25];
    const float* mrow = g_M + (e * 96 + tid) * NF;
#pragma unroll
    for (int p = 0; p < 25; p++) m2[p] = pack2(mrow[2 * p], mrow[2 * p + 1]);
    float cc = g_c[s * 96 + tid];
    __syncthreads();

    float* dst = g_xg0 + ((size_t)s * NL + t0) * 96 + tid;
    for (int tt = 0; tt < TT; tt++) {
        const ull* x2 = (const ull*)(xs + tt * 52);
        ull acc2 = 0ULL;
#pragma unroll
        for (int p = 0; p < 25; p++) fma2(acc2, m2[p], x2[p]);
        dst[(size_t)tt * 96] = hsum2(acc2) + cc;
    }
}

// ---- K5: recurrent kernel. 1 block = 1 chain = 3 warps (Whh0 | Wih1 | Whh1 in regs) ----
__global__ __launch_bounds__(96, 4) void k_rec(
    const float* __restrict__ Whh0, const float* __restrict__ bhh0,
    const float* __restrict__ Wih1, const float* __restrict__ Whh1,
    const float* __restrict__ bih1, const float* __restrict__ bhh1,
    const float* __restrict__ Wh1,  const float* __restrict__ bh1,
    const float* __restrict__ Wh2,  const float* __restrict__ bh2)
{
    int s = blockIdx.x;
    int e = g_ce[s];
    int lane = threadIdx.x & 31;
    int warp = threadIdx.x >> 5;

    __shared__ __align__(16) float h0_sm[32];
    __shared__ __align__(16) float h1_sm[32];
    __shared__ __align__(16) float xg1_sm[96];

    const float* Wbase = (warp == 0) ? (Whh0 + e * 96 * NH)
                       : (warp == 1) ? (Wih1 + e * 96 * NH)
                                     : (Whh1 + e * 96 * NH);
    // lane i owns rows i (r), 32+i (z), 64+i (n); packed as 16 f32x2 each
    ull W2r[16], W2z[16], W2n[16];
#pragma unroll
    for (int p = 0; p < 16; p++) {
        W2r[p] = pack2(Wbase[lane * NH + 2 * p],        Wbase[lane * NH + 2 * p + 1]);
        W2z[p] = pack2(Wbase[(32 + lane) * NH + 2 * p], Wbase[(32 + lane) * NH + 2 * p + 1]);
        W2n[p] = pack2(Wbase[(64 + lane) * NH + 2 * p], Wbase[(64 + lane) * NH + 2 * p + 1]);
    }
    float cr = 0.f, cz = 0.f, cn = 0.f;
    if (warp == 0) {
        cn = bhh0[e * 96 + 64 + lane];                      // bhh0_n (goes inside r*(.))
    } else if (warp == 1) {
        cr = bih1[e * 96 + lane]      + bhh1[e * 96 + lane];
        cz = bih1[e * 96 + 32 + lane] + bhh1[e * 96 + 32 + lane];
        cn = bih1[e * 96 + 64 + lane];                      // bhh1_n handled by warp 2
    } else {
        cn = bhh1[e * 96 + 64 + lane];
    }

    float h = 0.f;   // warp0: h0[lane]; warp2: h1[lane]
    if (threadIdx.x < 32) { h0_sm[threadIdx.x] = 0.f; h1_sm[threadIdx.x] = 0.f; }
    __syncthreads();

    const float* xg = g_xg0 + (size_t)s * NL * 96;
    float xr = 0.f, xz = 0.f, xn = 0.f;
    if (warp == 0) { xr = xg[lane]; xz = xg[32 + lane]; xn = xg[64 + lane]; }

    float gr1 = 0.f, gz1 = 0.f, gn1 = 0.f;

    for (int t = 0; t < NL; t++) {
        if (warp == 0) {
            // gh0 = Whh0 . h0(t-1); then full layer-0 cell
            const ull* h2 = (const ull*)h0_sm;
            ull ar = 0ULL, az = 0ULL, an = 0ULL;
#pragma unroll
            for (int p = 0; p < 16; p++) {
                ull hv = h2[p];
                fma2(ar, W2r[p], hv); fma2(az, W2z[p], hv); fma2(an, W2n[p], hv);
            }
            float r = sigm(xr + hsum2(ar));
            float z = sigm(xz + hsum2(az));
            float n = tanh_f(xn + r * (hsum2(an) + cn));
            h = (1.f - z) * n + z * h;
            h0_sm[lane] = h;
            if (t + 1 < NL) {   // prefetch next xg0 triple
                const float* p = xg + (size_t)(t + 1) * 96;
                xr = p[lane]; xz = p[32 + lane]; xn = p[64 + lane];
            }
        } else if (warp == 2) {
            // gh1 = Whh1 . h1(t-1) (overlaps with warp 0)
            const ull* h2 = (const ull*)h1_sm;
            ull ar = 0ULL, az = 0ULL, an = 0ULL;
#pragma unroll
            for (int p = 0; p < 16; p++) {
                ull hv = h2[p];
                fma2(ar, W2r[p], hv); fma2(az, W2z[p], hv); fma2(an, W2n[p], hv);
            }
            gr1 = hsum2(ar); gz1 = hsum2(az); gn1 = hsum2(an) + cn;
        }
        __syncthreads();   // h0(t) published
        if (warp == 1) {
            // xg1 = Wih1 . h0(t) + biases
            const ull* h2 = (const ull*)h0_sm;
            ull ar = 0ULL, az = 0ULL, an = 0ULL;
#pragma unroll
            for (int p = 0; p < 16; p++) {
                ull hv = h2[p];
                fma2(ar, W2r[p], hv); fma2(az, W2z[p], hv); fma2(an, W2n[p], hv);
            }
            xg1_sm[lane]      = hsum2(ar) + cr;
            xg1_sm[32 + lane] = hsum2(az) + cz;
            xg1_sm[64 + lane] = hsum2(an) + cn;
        }
        __syncthreads();   // xg1(t) published
        if (warp == 2) {
            float r = sigm(xg1_sm[lane] + gr1);
            float z = sigm(xg1_sm[32 + lane] + gz1);
            float n = tanh_f(xg1_sm[64 + lane] + r * gn1);
            h = (1.f - z) * n + z * h;
            h1_sm[lane] = h;
        }
    }
    __syncthreads();

    if (warp == 0) {
        // head MLP: lane = hidden unit u
        float acc = bh1[e * 32 + lane];
#pragma unroll
        for (int j = 0; j < NH; j++) acc += Wh1[(e * 32 + lane) * NH + j] * h1_sm[j];
        float hid = fmaxf(acc, 0.f);
        float v = Wh2[e * 32 + lane] * hid;
#pragma unroll
        for (int off = 16; off > 0; off >>= 1) v += __shfl_down_sync(0xffffffffu, v, off);
        if (lane == 0) g_predw[s] = g_cw[s] * (v + bh2[e]);
    }
}

// ---- K6: combine the two routed chains per batch ----
__global__ void k_final(float* __restrict__ out) {
    int b = threadIdx.x;
    out[b] = g_predw[2 * b] + g_predw[2 * b + 1];
}

extern "C" void kernel_launch(void* const* d_in, const int* in_sizes, int n_in,
                              void* d_out, int out_size) {
    const float* x       = (const float*)d_in[0];
    const int*   horizon = (const int*)  d_in[1];
    const float* W_in    = (const float*)d_in[2];
    const float* b_in    = (const float*)d_in[3];
    const float* emb     = (const float*)d_in[4];
    const float* W_gate  = (const float*)d_in[5];
    const float* b_gate  = (const float*)d_in[6];
    const float* Wih0    = (const float*)d_in[7];
    const float* Whh0    = (const float*)d_in[8];
    const float* bih0    = (const float*)d_in[9];
    const float* bhh0    = (const float*)d_in[10];
    const float* Wih1    = (const float*)d_in[11];
    const float* Whh1    = (const float*)d_in[12];
    const float* bih1    = (const float*)d_in[13];
    const float* bhh1    = (const float*)d_in[14];
    const float* Wh1     = (const float*)d_in[15];
    const float* bh1     = (const float*)d_in[16];
    const float* Wh2     = (const float*)d_in[17];
    const float* bh2     = (const float*)d_in[18];
    float* out = (float*)d_out;

    k_gate<<<1, NB>>>(horizon, emb, W_gate, b_gate);
    k_M<<<dim3(NE, 96), 64>>>(Wih0, W_in);
    k_c<<<NS, 96>>>(horizon, b_in, emb, Wih0, bih0, bhh0);
    k_xg0<<<dim3(NS, NTILE), 96>>>(x);
    k_rec<<<NS, 96>>>(Whh0, bhh0, Wih1, Whh1, bih1, bhh1, Wh1, bh1, Wh2, bh2);
    k_final<<<1, NB>>>(out);
}

// round 5
// speedup vs baseline: 1.5609x; 1.5609x over previous
#include <cuda_runtime.h>
#include <cstdint>

// MoEGRU: B=256, L=1800, F=50, E=4, K=2, H=32, D=64, HU=32
#define NB 256
#define NL 1800
#define NF 50
#define NE 4
#define NH 32
#define ND 64
#define NS 512      // routed chains = B*K
#define TT 40       // time-tile for xg0 GEMM
#define NTILE 45    // 1800/40
#define RR 6        // recurrence pipeline batch (must divide NL, even)
#define NK (NL / RR) // 300 super-steps

typedef unsigned long long ull;

// ---- scratch (static device globals; no allocation allowed) ----
__device__ float g_xg0[(size_t)NS * NL * 96];   // 354 MB: precomputed input gates, layer 0
__device__ float g_M[NE * 96 * NF];             // fused W_in -> Wih0 matrix
__device__ float g_c[NS * 96];                  // per-chain constant (emb/bias folded)
__device__ int   g_ce[NS];                      // chain -> expert
__device__ float g_cw[NS];                      // chain -> routing weight
__device__ float g_predw[NS];                   // weighted per-chain prediction

// ---- packed f32x2 helpers (sm_103a dual-fp32 pipe) ----
__device__ __forceinline__ ull pack2(float lo, float hi) {
    ull r;
    asm("mov.b64 %0, {%1, %2};" : "=l"(r) : "f"(lo), "f"(hi));
    return r;
}
__device__ __forceinline__ void fma2(ull &acc, ull a, ull b) {
    asm("fma.rn.f32x2 %0, %1, %2, %0;" : "+l"(acc) : "l"(a), "l"(b));
}
__device__ __forceinline__ float hsum2(ull v) {
    float lo, hi;
    asm("mov.b64 {%0, %1}, %2;" : "=f"(lo), "=f"(hi) : "l"(v));
    return lo + hi;
}

__device__ __forceinline__ float sigm(float x) { return 1.f / (1.f + __expf(-x)); }
__device__ __forceinline__ float tanh_f(float x) {
    float e = __expf(2.f * x);
    return 1.f - 2.f / (e + 1.f);
}

// 96x32 matvec (3 gate blocks), weights as 3x16 f32x2 regs, 6 accumulators.
__device__ __forceinline__ void matvec3(const ull* __restrict__ h2,
                                        const ull* Wr, const ull* Wz, const ull* Wn,
                                        float& orr, float& oz, float& on) {
    ull ar0 = 0ULL, ar1 = 0ULL, az0 = 0ULL, az1 = 0ULL, an0 = 0ULL, an1 = 0ULL;
#pragma unroll
    for (int p = 0; p < 16; p += 2) {
        ull hv0 = h2[p], hv1 = h2[p + 1];
        fma2(ar0, Wr[p], hv0); fma2(ar1, Wr[p + 1], hv1);
        fma2(az0, Wz[p], hv0); fma2(az1, Wz[p + 1], hv1);
        fma2(an0, Wn[p], hv0); fma2(an1, Wn[p + 1], hv1);
    }
    orr = hsum2(ar0) + hsum2(ar1);
    oz  = hsum2(az0) + hsum2(az1);
    on  = hsum2(an0) + hsum2(an1);
}

// ---- K1: gating (top-2 softmax) + chain assignment ----
__global__ void k_gate(const int* __restrict__ horizon, const float* __restrict__ emb,
                       const float* __restrict__ W_gate, const float* __restrict__ b_gate) {
    int b = threadIdx.x;
    const float* ev = emb + (size_t)horizon[b] * ND;
    float l[NE];
#pragma unroll
    for (int e = 0; e < NE; e++) {
        float acc = b_gate[e];
        for (int d = 0; d < ND; d++) acc += W_gate[e * ND + d] * ev[d];
        l[e] = acc;
    }
    int i0 = 0;
#pragma unroll
    for (int e = 1; e < NE; e++) if (l[e] > l[i0]) i0 = e;
    int i1 = -1;
#pragma unroll
    for (int e = 0; e < NE; e++) if (e != i0 && (i1 < 0 || l[e] > l[i1])) i1 = e;
    float ex = __expf(l[i1] - l[i0]);   // l[i0] is the max
    float w0 = 1.f / (1.f + ex);
    g_ce[2 * b] = i0;     g_cw[2 * b] = w0;
    g_ce[2 * b + 1] = i1; g_cw[2 * b + 1] = ex * w0;
}

// ---- K2: M[e][g][f] = sum_d Wih0[e][g][d] * W_in[d][f] ----
__global__ void k_M(const float* __restrict__ Wih0, const float* __restrict__ W_in) {
    int e = blockIdx.x, g = blockIdx.y, f = threadIdx.x;
    if (f >= NF) return;
    float acc = 0.f;
    for (int d = 0; d < ND; d++) acc += Wih0[(e * 96 + g) * ND + d] * W_in[d * NF + f];
    g_M[(e * 96 + g) * NF + f] = acc;
}

// ---- K3: chain constants: (b_in + emb[h_b]) . Wih0 + bih0 (+ bhh0 for r,z) ----
__global__ void k_c(const int* __restrict__ horizon, const float* __restrict__ b_in,
                    const float* __restrict__ emb, const float* __restrict__ Wih0,
                    const float* __restrict__ bih0, const float* __restrict__ bhh0) {
    int s = blockIdx.x, g = threadIdx.x;
    int b = s >> 1, e = g_ce[s];
    __shared__ float v[ND];
    if (g < ND) v[g] = b_in[g] + emb[(size_t)horizon[b] * ND + g];
    __syncthreads();
    float acc = bih0[e * 96 + g] + (g < 64 ? bhh0[e * 96 + g] : 0.f);  // bhh0_n stays with r*gh_n
#pragma unroll 8
    for (int d = 0; d < ND; d++) acc += Wih0[(e * 96 + g) * ND + d] * v[d];
    g_c[s * 96 + g] = acc;
}

// ---- K4: xg0 for BOTH chains of batch b in one block (shared x, 4 accs each) ----
__global__ __launch_bounds__(96, 4) void k_xg0(const float* __restrict__ x) {
    int b = blockIdx.x, tile = blockIdx.y;
    int t0 = tile * TT;
    int tid = threadIdx.x;
    int e0 = g_ce[2 * b], e1 = g_ce[2 * b + 1];
    __shared__ __align__(16) float xs[TT * 52];   // 52-float row stride (8B-aligned pairs)
    const float* xsrc = x + ((size_t)b * NL + t0) * NF;
    for (int idx = tid; idx < TT * NF; idx += 96)
        xs[(idx / NF) * 52 + (idx % NF)] = xsrc[idx];

    ull ma[25], mb[25];
    const float* ra = g_M + (e0 * 96 + tid) * NF;
    const float* rb = g_M + (e1 * 96 + tid) * NF;
#pragma unroll
    for (int p = 0; p < 25; p++) {
        ma[p] = pack2(ra[2 * p], ra[2 * p + 1]);
        mb[p] = pack2(rb[2 * p], rb[2 * p + 1]);
    }
    float ca = g_c[(2 * b) * 96 + tid];
    float cb = g_c[(2 * b + 1) * 96 + tid];
    __syncthreads();

    float* da = g_xg0 + ((size_t)(2 * b) * NL + t0) * 96 + tid;
    float* db = g_xg0 + ((size_t)(2 * b + 1) * NL + t0) * 96 + tid;
    for (int tt = 0; tt < TT; tt++) {
        const ull* x2 = (const ull*)(xs + tt * 52);
        ull a0 = 0ULL, a1 = 0ULL, a2 = 0ULL, a3 = 0ULL;
        ull b0 = 0ULL, b1 = 0ULL, b2 = 0ULL, b3 = 0ULL;
#pragma unroll
        for (int p = 0; p < 24; p += 4) {
            ull xv0 = x2[p], xv1 = x2[p + 1], xv2 = x2[p + 2], xv3 = x2[p + 3];
            fma2(a0, ma[p], xv0);     fma2(b0, mb[p], xv0);
            fma2(a1, ma[p + 1], xv1); fma2(b1, mb[p + 1], xv1);
            fma2(a2, ma[p + 2], xv2); fma2(b2, mb[p + 2], xv2);
            fma2(a3, ma[p + 3], xv3); fma2(b3, mb[p + 3], xv3);
        }
        { ull xv = x2[24]; fma2(a0, ma[24], xv); fma2(b0, mb[24], xv); }
        da[(size_t)tt * 96] = (hsum2(a0) + hsum2(a1)) + (hsum2(a2) + hsum2(a3)) + ca;
        db[(size_t)tt * 96] = (hsum2(b0) + hsum2(b1)) + (hsum2(b2) + hsum2(b3)) + cb;
    }
}

// ---- K5: recurrent kernel, 3-stage software pipeline over super-steps of RR ----
// warp0: layer-0 cell for batch k        -> h0buf[k&1]
// warp1: Wih1 . h0 for batch k-1         -> xgbuf[(k-1)&1]
// warp2: layer-1 cell for batch k-2      (reads xgbuf[(k-2)&1])
// one __syncthreads per super-step (RR steps).
__global__ __launch_bounds__(96, 4) void k_rec(
    const float* __restrict__ Whh0, const float* __restrict__ bhh0,
    const float* __restrict__ Wih1, const float* __restrict__ Whh1,
    const float* __restrict__ bih1, const float* __restrict__ bhh1,
    const float* __restrict__ Wh1,  const float* __restrict__ bh1,
    const float* __restrict__ Wh2,  const float* __restrict__ bh2)
{
    int s = blockIdx.x;
    int e = g_ce[s];
    int lane = threadIdx.x & 31;
    int warp = threadIdx.x >> 5;

    __shared__ __align__(16) float h0buf[2][RR][32];   // warp0 -> warp1 (+self ring)
    __shared__ __align__(16) float xgbuf[2][RR][96];   // warp1 -> warp2
    __shared__ __align__(16) float h1tmp[2][32];       // warp2 self (parity ring)

    const float* Wbase = (warp == 0) ? (Whh0 + e * 96 * NH)
                       : (warp == 1) ? (Wih1 + e * 96 * NH)
                                     : (Whh1 + e * 96 * NH);
    ull W2r[16], W2z[16], W2n[16];
#pragma unroll
    for (int p = 0; p < 16; p++) {
        W2r[p] = pack2(Wbase[lane * NH + 2 * p],        Wbase[lane * NH + 2 * p + 1]);
        W2z[p] = pack2(Wbase[(32 + lane) * NH + 2 * p], Wbase[(32 + lane) * NH + 2 * p + 1]);
        W2n[p] = pack2(Wbase[(64 + lane) * NH + 2 * p], Wbase[(64 + lane) * NH + 2 * p + 1]);
    }
    float cr = 0.f, cz = 0.f, cn = 0.f;
    if (warp == 0) {
        cn = bhh0[e * 96 + 64 + lane];                      // bhh0_n (inside r*(.))
    } else if (warp == 1) {
        cr = bih1[e * 96 + lane]      + bhh1[e * 96 + lane];
        cz = bih1[e * 96 + 32 + lane] + bhh1[e * 96 + 32 + lane];
        cn = bih1[e * 96 + 64 + lane];
    } else {
        cn = bhh1[e * 96 + 64 + lane];                      // bhh1_n (inside r*(.))
    }

    // zero-init ring entry points
    if (threadIdx.x < 32) {
        h0buf[1][RR - 1][threadIdx.x] = 0.f;   // read by warp0 at k=0, j=0
        h1tmp[1][threadIdx.x] = 0.f;           // read by warp2 at t=0 (parity 1)
    }
    __syncthreads();

    const float* xg = g_xg0 + (size_t)s * NL * 96;
    float h = 0.f;              // warp0: h0[lane]; warp2: h1[lane]
    float xc[3 * RR];           // warp0: current super-step's xg0 feed
    if (warp == 0) {
#pragma unroll
        for (int j = 0; j < RR; j++) {
            const float* p = xg + (size_t)j * 96;
            xc[3 * j] = p[lane]; xc[3 * j + 1] = p[32 + lane]; xc[3 * j + 2] = p[64 + lane];
        }
    }

    for (int k = 0; k <= NK + 1; k++) {
        int buf = k & 1;
        if (warp == 0) {
            if (k < NK) {
                float xn_[3 * RR];
                bool more = (k + 1 < NK);
                if (more) {
#pragma unroll
                    for (int j = 0; j < RR; j++) {
                        const float* p = xg + ((size_t)(k + 1) * RR + j) * 96;
                        xn_[3 * j] = p[lane]; xn_[3 * j + 1] = p[32 + lane]; xn_[3 * j + 2] = p[64 + lane];
                    }
                }
#pragma unroll
                for (int j = 0; j < RR; j++) {
                    const ull* h2 = (j == 0) ? (const ull*)&h0buf[buf ^ 1][RR - 1][0]
                                             : (const ull*)&h0buf[buf][j - 1][0];
                    float gr, gz, gn;
                    matvec3(h2, W2r, W2z, W2n, gr, gz, gn);
                    float r = sigm(xc[3 * j] + gr);
                    float z = sigm(xc[3 * j + 1] + gz);
                    float n = tanh_f(xc[3 * j + 2] + r * (gn + cn));
                    h = (1.f - z) * n + z * h;
                    h0buf[buf][j][lane] = h;
                    __syncwarp();
                }
                if (more) {
#pragma unroll
                    for (int i = 0; i < 3 * RR; i++) xc[i] = xn_[i];
                }
            }
        } else if (warp == 1) {
            if (k >= 1 && k <= NK) {
                int kb = buf ^ 1;   // (k-1)&1
#pragma unroll
                for (int j = 0; j < RR; j++) {
                    const ull* h2 = (const ull*)&h0buf[kb][j][0];
                    float gr, gz, gn;
                    matvec3(h2, W2r, W2z, W2n, gr, gz, gn);
                    xgbuf[kb][j][lane]      = gr + cr;
                    xgbuf[kb][j][32 + lane] = gz + cz;
                    xgbuf[kb][j][64 + lane] = gn + cn;
                }
            }
        } else {
            if (k >= 2) {
                int kb = buf;       // (k-2)&1
#pragma unroll
                for (int j = 0; j < RR; j++) {
                    const ull* h2 = (const ull*)&h1tmp[(j & 1) ^ 1][0];
                    float gr1, gz1, gn1;
                    matvec3(h2, W2r, W2z, W2n, gr1, gz1, gn1);
                    float r = sigm(xgbuf[kb][j][lane] + gr1);
                    float z = sigm(xgbuf[kb][j][32 + lane] + gz1);
                    float n = tanh_f(xgbuf[kb][j][64 + lane] + r * (gn1 + cn));
                    h = (1.f - z) * n + z * h;
                    h1tmp[j & 1][lane] = h;
                    __syncwarp();
                }
            }
        }
        __syncthreads();
    }

    // final h1 lives in h1tmp[1] (last step t=1799, parity 1); barrier above published it
    if (warp == 0) {
        float acc = bh1[e * 32 + lane];
#pragma unroll
        for (int j = 0; j < NH; j++) acc += Wh1[(e * 32 + lane) * NH + j] * h1tmp[1][j];
        float hid = fmaxf(acc, 0.f);
        float v = Wh2[e * 32 + lane] * hid;
#pragma unroll
        for (int off = 16; off > 0; off >>= 1) v += __shfl_down_sync(0xffffffffu, v, off);
        if (lane == 0) g_predw[s] = g_cw[s] * (v + bh2[e]);
    }
}

// ---- K6: combine the two routed chains per batch ----
__global__ void k_final(float* __restrict__ out) {
    int b = threadIdx.x;
    out[b] = g_predw[2 * b] + g_predw[2 * b + 1];
}

extern "C" void kernel_launch(void* const* d_in, const int* in_sizes, int n_in,
                              void* d_out, int out_size) {
    const float* x       = (const float*)d_in[0];
    const int*   horizon = (const int*)  d_in[1];
    const float* W_in    = (const float*)d_in[2];
    const float* b_in    = (const float*)d_in[3];
    const float* emb     = (const float*)d_in[4];
    const float* W_gate  = (const float*)d_in[5];
    const float* b_gate  = (const float*)d_in[6];
    const float* Wih0    = (const float*)d_in[7];
    const float* Whh0    = (const float*)d_in[8];
    const float* bih0    = (const float*)d_in[9];
    const float* bhh0    = (const float*)d_in[10];
    const float* Wih1    = (const float*)d_in[11];
    const float* Whh1    = (const float*)d_in[12];
    const float* bih1    = (const float*)d_in[13];
    const float* bhh1    = (const float*)d_in[14];
    const float* Wh1     = (const float*)d_in[15];
    const float* bh1     = (const float*)d_in[16];
    const float* Wh2     = (const float*)d_in[17];
    const float* bh2     = (const float*)d_in[18];
    float* out = (float*)d_out;

    k_gate<<<1, NB>>>(horizon, emb, W_gate, b_gate);
    k_M<<<dim3(NE, 96), 64>>>(Wih0, W_in);
    k_c<<<NS, 96>>>(horizon, b_in, emb, Wih0, bih0, bhh0);
    k_xg0<<<dim3(NB, NTILE), 96>>>(x);
    k_rec<<<NS, 96>>>(Whh0, bhh0, Wih1, Whh1, bih1, bhh1, Wh1, bh1, Wh2, bh2);
    k_final<<<1, NB>>>(out);
}

// round 7
// speedup vs baseline: 1.7132x; 1.0976x over previous
#include <cuda_runtime.h>
#include <cstdint>

// MoEGRU: B=256, L=1800, F=50, E=4, K=2, H=32, D=64, HU=32
#define NB 256
#define NL 1800
#define NF 50
#define NE 4
#define NH 32
#define ND 64
#define NS 512      // routed chains = B*K
#define TT 40       // time-tile for xg0 GEMM
#define NTILE 45    // 1800/40
#define RR 4        // recurrence pipeline batch (must divide NL, even)
#define NK (NL / RR) // 450 super-steps
#define MAXP 260    // max chain pairs (512/2 + up to 4 odd-bucket pads)

typedef unsigned long long ull;

// ---- scratch (static device globals; no allocation allowed) ----
__device__ float g_xg0[(size_t)NS * NL * 96];   // 354 MB: precomputed input gates, layer 0
__device__ float g_M[NE * 96 * NF];             // fused W_in -> Wih0 matrix
__device__ float g_c[NS * 96];                  // per-chain constant (emb/bias folded)
__device__ int   g_ce[NS];                      // chain -> expert
__device__ float g_cw[NS];                      // chain -> routing weight
__device__ float g_predw[NS];                   // weighted per-chain prediction
__device__ int   g_pairA[MAXP], g_pairB[MAXP];  // same-expert chain pairs
__device__ int   g_npair;

// ---- packed f32x2 helpers (sm_103a dual-fp32 pipe) ----
__device__ __forceinline__ ull pack2(float lo, float hi) {
    ull r;
    asm("mov.b64 %0, {%1, %2};" : "=l"(r) : "f"(lo), "f"(hi));
    return r;
}
__device__ __forceinline__ void fma2(ull &acc, ull a, ull b) {
    asm("fma.rn.f32x2 %0, %1, %2, %0;" : "+l"(acc) : "l"(a), "l"(b));
}
__device__ __forceinline__ float hsum2(ull v) {
    float lo, hi;
    asm("mov.b64 {%0, %1}, %2;" : "=f"(lo), "=f"(hi) : "l"(v));
    return lo + hi;
}

// fast activations: MUFU.RCP instead of IEEE divide (serial-chain killer)
__device__ __forceinline__ float frcp(float x) {
    float r;
    asm("rcp.approx.f32 %0, %1;" : "=f"(r) : "f"(x));
    return r;
}
__device__ __forceinline__ float sigm(float x) { return frcp(1.f + __expf(-x)); }
__device__ __forceinline__ float tanh_f(float x) {
    return fmaf(-2.f, frcp(1.f + __expf(2.f * x)), 1.f);
}

// dual-chain 96x32 matvec: shared weights, 6 accumulators (2 chains x 3 gates)
__device__ __forceinline__ void matvec3x2(const float* __restrict__ hA, const float* __restrict__ hB,
                                          const ull* Wr, const ull* Wz, const ull* Wn,
                                          float& grA, float& gzA, float& gnA,
                                          float& grB, float& gzB, float& gnB) {
    const ulonglong2* a4 = (const ulonglong2*)hA;
    const ulonglong2* b4 = (const ulonglong2*)hB;
    ull arA = 0, azA = 0, anA = 0, arB = 0, azB = 0, anB = 0;
#pragma unroll
    for (int p = 0; p < 8; p++) {
        ulonglong2 va = a4[p], vb = b4[p];
        fma2(arA, Wr[2 * p], va.x); fma2(arA, Wr[2 * p + 1], va.y);
        fma2(azA, Wz[2 * p], va.x); fma2(azA, Wz[2 * p + 1], va.y);
        fma2(anA, Wn[2 * p], va.x); fma2(anA, Wn[2 * p + 1], va.y);
        fma2(arB, Wr[2 * p], vb.x); fma2(arB, Wr[2 * p + 1], vb.y);
        fma2(azB, Wz[2 * p], vb.x); fma2(azB, Wz[2 * p + 1], vb.y);
        fma2(anB, Wn[2 * p], vb.x); fma2(anB, Wn[2 * p + 1], vb.y);
    }
    grA = hsum2(arA); gzA = hsum2(azA); gnA = hsum2(anA);
    grB = hsum2(arB); gzB = hsum2(azB); gnB = hsum2(anB);
}

// ---- K1: gating (top-2 softmax) + deterministic same-expert chain pairing ----
__global__ void k_gate(const int* __restrict__ horizon, const float* __restrict__ emb,
                       const float* __restrict__ W_gate, const float* __restrict__ b_gate) {
    __shared__ int sce[NS];
    int b = threadIdx.x;
    const float* ev = emb + (size_t)horizon[b] * ND;
    float l[NE];
#pragma unroll
    for (int e = 0; e < NE; e++) {
        float acc = b_gate[e];
        for (int d = 0; d < ND; d++) acc += W_gate[e * ND + d] * ev[d];
        l[e] = acc;
    }
    int i0 = 0;
#pragma unroll
    for (int e = 1; e < NE; e++) if (l[e] > l[i0]) i0 = e;
    int i1 = -1;
#pragma unroll
    for (int e = 0; e < NE; e++) if (e != i0 && (i1 < 0 || l[e] > l[i1])) i1 = e;
    float ex = __expf(l[i1] - l[i0]);   // l[i0] is the max
    float w0 = 1.f / (1.f + ex);
    g_ce[2 * b] = i0;     g_cw[2 * b] = w0;
    g_ce[2 * b + 1] = i1; g_cw[2 * b + 1] = ex * w0;
    sce[2 * b] = i0; sce[2 * b + 1] = i1;
    __syncthreads();
    if (b == 0) {
        int p0 = -1, p1 = -1, p2 = -1, p3 = -1, np = 0;
        for (int s = 0; s < NS; s++) {
            int e = sce[s];
            if (e == 0)      { if (p0 < 0) p0 = s; else { g_pairA[np] = p0; g_pairB[np] = s; np++; p0 = -1; } }
            else if (e == 1) { if (p1 < 0) p1 = s; else { g_pairA[np] = p1; g_pairB[np] = s; np++; p1 = -1; } }
            else if (e == 2) { if (p2 < 0) p2 = s; else { g_pairA[np] = p2; g_pairB[np] = s; np++; p2 = -1; } }
            else             { if (p3 < 0) p3 = s; else { g_pairA[np] = p3; g_pairB[np] = s; np++; p3 = -1; } }
        }
        if (p0 >= 0) { g_pairA[np] = p0; g_pairB[np] = p0; np++; }
        if (p1 >= 0) { g_pairA[np] = p1; g_pairB[np] = p1; np++; }
        if (p2 >= 0) { g_pairA[np] = p2; g_pairB[np] = p2; np++; }
        if (p3 >= 0) { g_pairA[np] = p3; g_pairB[np] = p3; np++; }
        g_npair = np;
    }
}

// ---- K2: M[e][g][f] = sum_d Wih0[e][g][d] * W_in[d][f] ----
__global__ void k_M(const float* __restrict__ Wih0, const float* __restrict__ W_in) {
    int e = blockIdx.x, g = blockIdx.y, f = threadIdx.x;
    if (f >= NF) return;
    float acc = 0.f;
    for (int d = 0; d < ND; d++) acc += Wih0[(e * 96 + g) * ND + d] * W_in[d * NF + f];
    g_M[(e * 96 + g) * NF + f] = acc;
}

// ---- K3: chain constants: (b_in + emb[h_b]) . Wih0 + bih0 (+ bhh0 for r,z) ----
__global__ void k_c(const int* __restrict__ horizon, const float* __restrict__ b_in,
                    const float* __restrict__ emb, const float* __restrict__ Wih0,
                    const float* __restrict__ bih0, const float* __restrict__ bhh0) {
    int s = blockIdx.x, g = threadIdx.x;
    int b = s >> 1, e = g_ce[s];
    __shared__ float v[ND];
    if (g < ND) v[g] = b_in[g] + emb[(size_t)horizon[b] * ND + g];
    __syncthreads();
    float acc = bih0[e * 96 + g] + (g < 64 ? bhh0[e * 96 + g] : 0.f);  // bhh0_n stays with r*gh_n
#pragma unroll 8
    for (int d = 0; d < ND; d++) acc += Wih0[(e * 96 + g) * ND + d] * v[d];
    g_c[s * 96 + g] = acc;
}

// ---- K4: xg0 for BOTH chains of batch b in one block (shared x, LDS.128 feeds) ----
__global__ __launch_bounds__(96, 4) void k_xg0(const float* __restrict__ x) {
    int b = blockIdx.x, tile = blockIdx.y;
    int t0 = tile * TT;
    int tid = threadIdx.x;
    int e0 = g_ce[2 * b], e1 = g_ce[2 * b + 1];
    __shared__ __align__(16) float xs[TT * 52];   // 52-float row stride (16B-aligned rows)
    const float* xsrc = x + ((size_t)b * NL + t0) * NF;
    for (int idx = tid; idx < TT * NF; idx += 96)
        xs[(idx / NF) * 52 + (idx % NF)] = xsrc[idx];
    for (int r = tid; r < TT; r += 96) { xs[r * 52 + 50] = 0.f; xs[r * 52 + 51] = 0.f; }

    ull ma[26], mb[26];
    const float* ra = g_M + (e0 * 96 + tid) * NF;
    const float* rb = g_M + (e1 * 96 + tid) * NF;
#pragma unroll
    for (int p = 0; p < 25; p++) {
        ma[p] = pack2(ra[2 * p], ra[2 * p + 1]);
        mb[p] = pack2(rb[2 * p], rb[2 * p + 1]);
    }
    ma[25] = 0ULL; mb[25] = 0ULL;   // pairs x pad (zeroed) contribute 0
    float ca = g_c[(2 * b) * 96 + tid];
    float cb = g_c[(2 * b + 1) * 96 + tid];
    __syncthreads();

    float* da = g_xg0 + ((size_t)(2 * b) * NL + t0) * 96 + tid;
    float* db = g_xg0 + ((size_t)(2 * b + 1) * NL + t0) * 96 + tid;
    for (int tt = 0; tt < TT; tt++) {
        const ulonglong2* x4 = (const ulonglong2*)(xs + tt * 52);
        ull a0 = 0, a1 = 0, a2 = 0, a3 = 0, b0 = 0, b1 = 0, b2 = 0, b3 = 0;
#pragma unroll
        for (int q = 0; q < 13; q++) {
            ulonglong2 v = x4[q];
            if (q & 1) {
                fma2(a2, ma[2 * q], v.x); fma2(a3, ma[2 * q + 1], v.y);
                fma2(b2, mb[2 * q], v.x); fma2(b3, mb[2 * q + 1], v.y);
            } else {
                fma2(a0, ma[2 * q], v.x); fma2(a1, ma[2 * q + 1], v.y);
                fma2(b0, mb[2 * q], v.x); fma2(b1, mb[2 * q + 1], v.y);
            }
        }
        da[(size_t)tt * 96] = (hsum2(a0) + hsum2(a1)) + (hsum2(a2) + hsum2(a3)) + ca;
        db[(size_t)tt * 96] = (hsum2(b0) + hsum2(b1)) + (hsum2(b2) + hsum2(b3)) + cb;
    }
}

// ---- K5: recurrent kernel. 1 block = 2 same-expert chains, 3 warps, shared weights.
// warp0: layer-0 cell for batch k        -> h0buf[c][k&1]
// warp1: Wih1 . h0 for batch k-1         -> xgbuf[c][(k-1)&1]
// warp2: layer-1 cell for batch k-2      (reads xgbuf[c][(k-2)&1])
__global__ __launch_bounds__(96, 2) void k_rec(
    const float* __restrict__ Whh0, const float* __restrict__ bhh0,
    const float* __restrict__ Wih1, const float* __restrict__ Whh1,
    const float* __restrict__ bih1, const float* __restrict__ bhh1,
    const float* __restrict__ Wh1,  const float* __restrict__ bh1,
    const float* __restrict__ Wh2,  const float* __restrict__ bh2)
{
    int np = g_npair;
    if ((int)blockIdx.x >= np) return;
    int sA = g_pairA[blockIdx.x], sB = g_pairB[blockIdx.x];
    int e = g_ce[sA];
    int lane = threadIdx.x & 31;
    int warp = threadIdx.x >> 5;

    __shared__ __align__(16) float h0buf[2][2][RR][32];   // [chain][buf][j][lane]
    __shared__ __align__(16) float xgbuf[2][2][RR][96];
    __shared__ __align__(16) float h1tmp[2][2][32];       // [chain][parity][lane]

    const float* Wbase = (warp == 0) ? (Whh0 + e * 96 * NH)
                       : (warp == 1) ? (Wih1 + e * 96 * NH)
                                     : (Whh1 + e * 96 * NH);
    ull W2r[16], W2z[16], W2n[16];
#pragma unroll
    for (int p = 0; p < 16; p++) {
        W2r[p] = pack2(Wbase[lane * NH + 2 * p],        Wbase[lane * NH + 2 * p + 1]);
        W2z[p] = pack2(Wbase[(32 + lane) * NH + 2 * p], Wbase[(32 + lane) * NH + 2 * p + 1]);
        W2n[p] = pack2(Wbase[(64 + lane) * NH + 2 * p], Wbase[(64 + lane) * NH + 2 * p + 1]);
    }
    float cr = 0.f, cz = 0.f, cn = 0.f;
    if (warp == 0) {
        cn = bhh0[e * 96 + 64 + lane];                      // bhh0_n (inside r*(.))
    } else if (warp == 1) {
        cr = bih1[e * 96 + lane]      + bhh1[e * 96 + lane];
        cz = bih1[e * 96 + 32 + lane] + bhh1[e * 96 + 32 + lane];
        cn = bih1[e * 96 + 64 + lane];
    } else {
        cn = bhh1[e * 96 + 64 + lane];                      // bhh1_n (inside r*(.))
    }

    if (threadIdx.x < 32) {
        h0buf[0][1][RR - 1][threadIdx.x] = 0.f;   // read by warp0 at k=0, j=0
        h0buf[1][1][RR - 1][threadIdx.x] = 0.f;
        h1tmp[0][1][threadIdx.x] = 0.f;           // read by warp2 at t=0 (parity 1)
        h1tmp[1][1][threadIdx.x] = 0.f;
    }
    __syncthreads();

    const float* xgA = g_xg0 + (size_t)sA * NL * 96;
    const float* xgB = g_xg0 + (size_t)sB * NL * 96;
    float hA = 0.f, hB = 0.f;     // warp0: h0; warp2: h1
    float xcA[3 * RR], xcB[3 * RR], xnA[3 * RR], xnB[3 * RR];
    if (warp == 0) {
#pragma unroll
        for (int j = 0; j < RR; j++) {
            const float* pA = xgA + (size_t)j * 96;
            const float* pB = xgB + (size_t)j * 96;
            xcA[3 * j] = pA[lane]; xcA[3 * j + 1] = pA[32 + lane]; xcA[3 * j + 2] = pA[64 + lane];
            xcB[3 * j] = pB[lane]; xcB[3 * j + 1] = pB[32 + lane]; xcB[3 * j + 2] = pB[64 + lane];
        }
    }

    for (int k = 0; k <= NK + 1; k++) {
        int buf = k & 1;
        if (warp == 0) {
            if (k < NK) {
                bool more = (k + 1 < NK);
                if (more) {
#pragma unroll
                    for (int j = 0; j < RR; j++) {
                        const float* pA = xgA + ((size_t)(k + 1) * RR + j) * 96;
                        const float* pB = xgB + ((size_t)(k + 1) * RR + j) * 96;
                        xnA[3 * j] = pA[lane]; xnA[3 * j + 1] = pA[32 + lane]; xnA[3 * j + 2] = pA[64 + lane];
                        xnB[3 * j] = pB[lane]; xnB[3 * j + 1] = pB[32 + lane]; xnB[3 * j + 2] = pB[64 + lane];
                    }
                }
#pragma unroll
                for (int j = 0; j < RR; j++) {
                    const float* hA2 = (j == 0) ? &h0buf[0][buf ^ 1][RR - 1][0] : &h0buf[0][buf][j - 1][0];
                    const float* hB2 = (j == 0) ? &h0buf[1][buf ^ 1][RR - 1][0] : &h0buf[1][buf][j - 1][0];
                    float grA, gzA, gnA, grB, gzB, gnB;
                    matvec3x2(hA2, hB2, W2r, W2z, W2n, grA, gzA, gnA, grB, gzB, gnB);
                    float rA = sigm(xcA[3 * j] + grA);
                    float zA = sigm(xcA[3 * j + 1] + gzA);
                    float nA = tanh_f(xcA[3 * j + 2] + rA * (gnA + cn));
                    hA = (1.f - zA) * nA + zA * hA;
                    float rB = sigm(xcB[3 * j] + grB);
                    float zB = sigm(xcB[3 * j + 1] + gzB);
                    float nB = tanh_f(xcB[3 * j + 2] + rB * (gnB + cn));
                    hB = (1.f - zB) * nB + zB * hB;
                    h0buf[0][buf][j][lane] = hA;
                    h0buf[1][buf][j][lane] = hB;
                    __syncwarp();
                }
                if (more) {
#pragma unroll
                    for (int i = 0; i < 3 * RR; i++) { xcA[i] = xnA[i]; xcB[i] = xnB[i]; }
                }
            }
        } else if (warp == 1) {
            if (k >= 1 && k <= NK) {
                int kb = buf ^ 1;   // (k-1)&1
#pragma unroll
                for (int j = 0; j < RR; j++) {
                    float grA, gzA, gnA, grB, gzB, gnB;
                    matvec3x2(&h0buf[0][kb][j][0], &h0buf[1][kb][j][0],
                              W2r, W2z, W2n, grA, gzA, gnA, grB, gzB, gnB);
                    xgbuf[0][kb][j][lane]      = grA + cr;
                    xgbuf[0][kb][j][32 + lane] = gzA + cz;
                    xgbuf[0][kb][j][64 + lane] = gnA + cn;
                    xgbuf[1][kb][j][lane]      = grB + cr;
                    xgbuf[1][kb][j][32 + lane] = gzB + cz;
                    xgbuf[1][kb][j][64 + lane] = gnB + cn;
                }
            }
        } else {
            if (k >= 2) {
                int kb = buf;       // (k-2)&1
#pragma unroll
                for (int j = 0; j < RR; j++) {
                    float grA, gzA, gnA, grB, gzB, gnB;
                    matvec3x2(&h1tmp[0][(j & 1) ^ 1][0], &h1tmp[1][(j & 1) ^ 1][0],
                              W2r, W2z, W2n, grA, gzA, gnA, grB, gzB, gnB);
                    float rA = sigm(xgbuf[0][kb][j][lane] + grA);
                    float zA = sigm(xgbuf[0][kb][j][32 + lane] + gzA);
                    float nA = tanh_f(xgbuf[0][kb][j][64 + lane] + rA * (gnA + cn));
                    hA = (1.f - zA) * nA + zA * hA;
                    float rB = sigm(xgbuf[1][kb][j][lane] + grB);
                    float zB = sigm(xgbuf[1][kb][j][32 + lane] + gzB);
                    float nB = tanh_f(xgbuf[1][kb][j][64 + lane] + rB * (gnB + cn));
                    hB = (1.f - zB) * nB + zB * hB;
                    h1tmp[0][j & 1][lane] = hA;
                    h1tmp[1][j & 1][lane] = hB;
                    __syncwarp();
                }
            }
        }
        __syncthreads();
    }

    // final h1 per chain in h1tmp[c][1] (last step parity 1); barrier published it
    if (warp < 2) {
        int s = warp ? sB : sA;
        const float* h1 = &h1tmp[warp][1][0];
        float acc = bh1[e * 32 + lane];
#pragma unroll
        for (int j = 0; j < NH; j++) acc += Wh1[(e * 32 + lane) * NH + j] * h1[j];
        float hid = fmaxf(acc, 0.f);
        float v = Wh2[e * 32 + lane] * hid;
#pragma unroll
        for (int off = 16; off > 0; off >>= 1) v += __shfl_down_sync(0xffffffffu, v, off);
        if (lane == 0) g_predw[s] = g_cw[s] * (v + bh2[e]);
    }
}

// ---- K6: combine the two routed chains per batch ----
__global__ void k_final(float* __restrict__ out) {
    int b = threadIdx.x;
    out[b] = g_predw[2 * b] + g_predw[2 * b + 1];
}

extern "C" void kernel_launch(void* const* d_in, const int* in_sizes, int n_in,
                              void* d_out, int out_size) {
    const float* x       = (const float*)d_in[0];
    const int*   horizon = (const int*)  d_in[1];
    const float* W_in    = (const float*)d_in[2];
    const float* b_in    = (const float*)d_in[3];
    const float* emb     = (const float*)d_in[4];
    const float* W_gate  = (const float*)d_in[5];
    const float* b_gate  = (const float*)d_in[6];
    const float* Wih0    = (const float*)d_in[7];
    const float* Whh0    = (const float*)d_in[8];
    const float* bih0    = (const float*)d_in[9];
    const float* bhh0    = (const float*)d_in[10];
    const float* Wih1    = (const float*)d_in[11];
    const float* Whh1    = (const float*)d_in[12];
    const float* bih1    = (const float*)d_in[13];
    const float* bhh1    = (const float*)d_in[14];
    const float* Wh1     = (const float*)d_in[15];
    const float* bh1     = (const float*)d_in[16];
    const float* Wh2     = (const float*)d_in[17];
    const float* bh2     = (const float*)d_in[18];
    float* out = (float*)d_out;

    k_gate<<<1, NB>>>(horizon, emb, W_gate, b_gate);
    k_M<<<dim3(NE, 96), 64>>>(Wih0, W_in);
    k_c<<<NS, 96>>>(horizon, b_in, emb, Wih0, bih0, bhh0);
    k_xg0<<<dim3(NB, NTILE), 96>>>(x);
    k_rec<<<MAXP, 96>>>(Whh0, bhh0, Wih1, Whh1, bih1, bhh1, Wh1, bh1, Wh2, bh2);
    k_final<<<1, NB>>>(out);
}